// round 1
// baseline (speedup 1.0000x reference)
#include <cuda_runtime.h>

#define BB 2
#define TT 2048
#define DD 1024
#define NH 16
#define NKV 4
#define DH 64
#define MM (BB*TT)   // 4096

// Scratch (device globals — no allocation allowed)
__device__ float g_q[MM*NH*DH];    // 16 MB
__device__ float g_k[MM*NKV*DH];   // 4 MB
__device__ float g_v[MM*NKV*DH];   // 4 MB
__device__ float g_ao[MM*NH*DH];   // 16 MB

// ---------------------------------------------------------------------------
// NT GEMM: C[m,n] = sum_k A[m,k] * W[n,k]. 64x64 tile, BK=16, 256 thr, 4x4/thr.
// ---------------------------------------------------------------------------
__global__ __launch_bounds__(256) void gemm_nt_kernel(
    const float* __restrict__ A, const float* __restrict__ W,
    float* __restrict__ C, int N, int K) {
  __shared__ float As[16][68];
  __shared__ float Ws[16][68];
  int tid = threadIdx.x;
  int tx = tid & 15, ty = tid >> 4;
  int mBase = blockIdx.y << 6;
  int nBase = blockIdx.x << 6;
  float acc[4][4] = {};
  int li = tid >> 2;          // 0..63
  int lj = (tid & 3) << 2;    // 0,4,8,12
  const float* Aptr = A + (size_t)(mBase + li) * K + lj;
  const float* Wptr = W + (size_t)(nBase + li) * K + lj;
  for (int k0 = 0; k0 < K; k0 += 16) {
    float4 av = *(const float4*)(Aptr + k0);
    float4 wv = *(const float4*)(Wptr + k0);
    As[lj  ][li] = av.x; As[lj+1][li] = av.y; As[lj+2][li] = av.z; As[lj+3][li] = av.w;
    Ws[lj  ][li] = wv.x; Ws[lj+1][li] = wv.y; Ws[lj+2][li] = wv.z; Ws[lj+3][li] = wv.w;
    __syncthreads();
#pragma unroll
    for (int kk = 0; kk < 16; kk++) {
      float4 a = *(const float4*)&As[kk][ty << 2];
      float4 b = *(const float4*)&Ws[kk][tx << 2];
      acc[0][0] += a.x*b.x; acc[0][1] += a.x*b.y; acc[0][2] += a.x*b.z; acc[0][3] += a.x*b.w;
      acc[1][0] += a.y*b.x; acc[1][1] += a.y*b.y; acc[1][2] += a.y*b.z; acc[1][3] += a.y*b.w;
      acc[2][0] += a.z*b.x; acc[2][1] += a.z*b.y; acc[2][2] += a.z*b.z; acc[2][3] += a.z*b.w;
      acc[3][0] += a.w*b.x; acc[3][1] += a.w*b.y; acc[3][2] += a.w*b.z; acc[3][3] += a.w*b.w;
    }
    __syncthreads();
  }
#pragma unroll
  for (int i = 0; i < 4; i++) {
    float4 r = make_float4(acc[i][0], acc[i][1], acc[i][2], acc[i][3]);
    *(float4*)&C[(size_t)(mBase + (ty << 2) + i) * N + nBase + (tx << 2)] = r;
  }
}

// ---------------------------------------------------------------------------
// RoPE on q (all 16 heads) and k (4 heads), in place. One thread per pair.
// ---------------------------------------------------------------------------
__global__ __launch_bounds__(256) void rope_kernel(const float* __restrict__ freqs) {
  int idx = blockIdx.x * blockDim.x + threadIdx.x;   // < MM*NH*32
  int i  = idx & 31;
  int h  = (idx >> 5) & 15;
  int bt = idx >> 9;                                  // b*T + t
  int t  = bt & (TT - 1);
  float c = freqs[(t * 32 + i) * 2];
  float s = freqs[(t * 32 + i) * 2 + 1];
  float* qp = &g_q[((size_t)bt * NH + h) * DH + 2 * i];
  float re = qp[0], im = qp[1];
  qp[0] = re * c - im * s;
  qp[1] = re * s + im * c;
  if (h < NKV) {
    float* kp = &g_k[((size_t)bt * NKV + h) * DH + 2 * i];
    float kre = kp[0], kim = kp[1];
    kp[0] = kre * c - kim * s;
    kp[1] = kre * s + kim * c;
  }
}

// ---------------------------------------------------------------------------
// Causal flash attention. Block = (q-tile of 64, b*H+h). 256 threads.
// K/V tiles of 32 keys. Thread: 4x2 of S, 4x4 of O. Online softmax with
// shfl reductions over the 16-lane row group.
// ---------------------------------------------------------------------------
__global__ __launch_bounds__(256) void attn_kernel() {
  __shared__ float Qs[64][68];   // [d][query]
  __shared__ float Ks[64][36];   // [d][key]
  __shared__ float Vs[32][68];   // [key][d]
  __shared__ float Ps[32][68];   // [key][query]
  int tid = threadIdx.x;
  int tx = tid & 15, ty = tid >> 4;
  int bh = blockIdx.y;
  int b = bh >> 4, h = bh & 15;
  int kvh = h >> 2;
  int q0 = blockIdx.x << 6;

  for (int l = tid; l < 4096; l += 256) {
    int r = l >> 6, d = l & 63;
    Qs[d][r] = g_q[(((size_t)b * TT + q0 + r) * NH + h) * DH + d];
  }

  float o[4][4] = {};
  float mrow[4] = {-1e30f, -1e30f, -1e30f, -1e30f};
  float lrow[4] = {};
  const float scale = 0.125f;   // 1/sqrt(64)
  int nk = q0 + 64;             // causal: keys [0, q0+64)

  for (int k0 = 0; k0 < nk; k0 += 32) {
    __syncthreads();  // prev PV done (and Qs ready on first iter)
    for (int l = tid; l < 2048; l += 256) {
      int j = l >> 6, d = l & 63;
      size_t base = (((size_t)b * TT + k0 + j) * NKV + kvh) * DH + d;
      Ks[d][j] = g_k[base];
      Vs[j][d] = g_v[base];
    }
    __syncthreads();

    // S = Q K^T (4 rows x 2 cols per thread)
    float s00=0,s01=0,s10=0,s11=0,s20=0,s21=0,s30=0,s31=0;
#pragma unroll
    for (int d = 0; d < 64; d++) {
      float4 a  = *(const float4*)&Qs[d][ty << 2];
      float2 bq = *(const float2*)&Ks[d][tx << 1];
      s00 += a.x*bq.x; s01 += a.x*bq.y;
      s10 += a.y*bq.x; s11 += a.y*bq.y;
      s20 += a.z*bq.x; s21 += a.z*bq.y;
      s30 += a.w*bq.x; s31 += a.w*bq.y;
    }
    float sarr[4][2] = {{s00,s01},{s10,s11},{s20,s21},{s30,s31}};

#pragma unroll
    for (int i = 0; i < 4; i++) {
      int qi = q0 + (ty << 2) + i;
      int kj = k0 + (tx << 1);
      float v0 = sarr[i][0] * scale + ((kj     > qi) ? -1e9f : 0.f);
      float v1 = sarr[i][1] * scale + ((kj + 1 > qi) ? -1e9f : 0.f);
      float mx = fmaxf(v0, v1);
#pragma unroll
      for (int off = 8; off > 0; off >>= 1)
        mx = fmaxf(mx, __shfl_xor_sync(0xffffffffu, mx, off, 16));
      float mnew = fmaxf(mrow[i], mx);
      float sf = __expf(mrow[i] - mnew);
      mrow[i] = mnew;
      float p0 = __expf(v0 - mnew);
      float p1 = __expf(v1 - mnew);
      float rs = p0 + p1;
#pragma unroll
      for (int off = 8; off > 0; off >>= 1)
        rs += __shfl_xor_sync(0xffffffffu, rs, off, 16);
      lrow[i] = lrow[i] * sf + rs;
      o[i][0] *= sf; o[i][1] *= sf; o[i][2] *= sf; o[i][3] *= sf;
      Ps[(tx << 1)    ][(ty << 2) + i] = p0;
      Ps[(tx << 1) + 1][(ty << 2) + i] = p1;
    }
    __syncthreads();  // Ps ready

    // O += P @ V
#pragma unroll
    for (int j = 0; j < 32; j++) {
      float4 p  = *(const float4*)&Ps[j][ty << 2];
      float4 vv = *(const float4*)&Vs[j][tx << 2];
      o[0][0] += p.x*vv.x; o[0][1] += p.x*vv.y; o[0][2] += p.x*vv.z; o[0][3] += p.x*vv.w;
      o[1][0] += p.y*vv.x; o[1][1] += p.y*vv.y; o[1][2] += p.y*vv.z; o[1][3] += p.y*vv.w;
      o[2][0] += p.z*vv.x; o[2][1] += p.z*vv.y; o[2][2] += p.z*vv.z; o[2][3] += p.z*vv.w;
      o[3][0] += p.w*vv.x; o[3][1] += p.w*vv.y; o[3][2] += p.w*vv.z; o[3][3] += p.w*vv.w;
    }
  }

#pragma unroll
  for (int i = 0; i < 4; i++) {
    float inv = 1.0f / lrow[i];
    float4 r = make_float4(o[i][0]*inv, o[i][1]*inv, o[i][2]*inv, o[i][3]*inv);
    *(float4*)&g_ao[(((size_t)b * TT + q0 + (ty << 2) + i) * NH + h) * DH + (tx << 2)] = r;
  }
}

// ---------------------------------------------------------------------------
// Launch
// ---------------------------------------------------------------------------
extern "C" void kernel_launch(void* const* d_in, const int* in_sizes, int n_in,
                              void* d_out, int out_size) {
  const float* x     = (const float*)d_in[0];
  const float* freqs = (const float*)d_in[1];
  // d_in[2] = mask (causal, known statically — unused)
  const float* w_q   = (const float*)d_in[3];
  const float* w_k   = (const float*)d_in[4];
  const float* w_v   = (const float*)d_in[5];
  const float* w_o   = (const float*)d_in[6];
  float* out = (float*)d_out;

  float *pq, *pk, *pv, *pao;
  cudaGetSymbolAddress((void**)&pq,  g_q);
  cudaGetSymbolAddress((void**)&pk,  g_k);
  cudaGetSymbolAddress((void**)&pv,  g_v);
  cudaGetSymbolAddress((void**)&pao, g_ao);

  // QKV projections
  gemm_nt_kernel<<<dim3(NH*DH/64,  MM/64), 256>>>(x, w_q, pq, NH*DH,  DD);
  gemm_nt_kernel<<<dim3(NKV*DH/64, MM/64), 256>>>(x, w_k, pk, NKV*DH, DD);
  gemm_nt_kernel<<<dim3(NKV*DH/64, MM/64), 256>>>(x, w_v, pv, NKV*DH, DD);

  // RoPE on q and k
  rope_kernel<<<(MM*NH*32)/256, 256>>>(freqs);

  // Causal flash attention
  attn_kernel<<<dim3(TT/64, BB*NH), 256>>>();

  // Output projection
  gemm_nt_kernel<<<dim3(DD/64, MM/64), 256>>>(pao, w_o, out, DD, DD);
}

// round 2
// speedup vs baseline: 4.1641x; 4.1641x over previous
#include <cuda_runtime.h>
#include <cstdint>

#define BB 2
#define TT 2048
#define DD 1024
#define NH 16
#define NKV 4
#define DH 64
#define MM (BB*TT)   // 4096

// Scratch (device globals — no allocation allowed)
__device__ float g_q[MM*NH*DH];    // 16 MB
__device__ float g_k[MM*NKV*DH];   // 4 MB
__device__ float g_v[MM*NKV*DH];   // 4 MB
__device__ float g_ao[MM*NH*DH];   // 16 MB

__device__ __forceinline__ uint32_t f2tf(float x) {
  uint32_t r;
  asm("cvt.rna.tf32.f32 %0, %1;" : "=r"(r) : "f"(x));
  return r;
}

__device__ __forceinline__ void mma8(float* c,
    uint32_t a0, uint32_t a1, uint32_t a2, uint32_t a3,
    uint32_t b0, uint32_t b1) {
  asm volatile(
    "mma.sync.aligned.m16n8k8.row.col.f32.tf32.tf32.f32 "
    "{%0,%1,%2,%3},{%4,%5,%6,%7},{%8,%9},{%0,%1,%2,%3};"
    : "+f"(c[0]), "+f"(c[1]), "+f"(c[2]), "+f"(c[3])
    : "r"(a0), "r"(a1), "r"(a2), "r"(a3), "r"(b0), "r"(b1));
}

// ---------------------------------------------------------------------------
// NT GEMM via tf32 MMA: C[m,n] = sum_k A[m,k]*W[n,k].
// 64x64 tile, BK=32, 256 threads (8 warps, warp tile 32x16), double-buffered.
// ---------------------------------------------------------------------------
#define GBM 64
#define GBN 64
#define GBK 32
__global__ __launch_bounds__(256) void gemm_mma(
    const float* __restrict__ A, const float* __restrict__ W,
    float* __restrict__ C, int N, int K) {
  __shared__ uint32_t As[2][GBM][GBK + 4];
  __shared__ uint32_t Ws[2][GBN][GBK + 4];
  int tid = threadIdx.x, lane = tid & 31, wid = tid >> 5;
  int wm = wid & 1;        // 0/1 -> 32 rows
  int wn = wid >> 1;       // 0..3 -> 16 cols
  int mBase = blockIdx.y * GBM;
  int nBase = blockIdx.x * GBN;
  int r = lane >> 2, c = lane & 3;

  // loader mapping: 64 rows, 32 cols; 256 thr -> row=tid>>2, seg=(tid&3)*8
  int arow = tid >> 2;
  int aseg = (tid & 3) * 8;
  const float* Ap = A + (size_t)(mBase + arow) * K + aseg;
  const float* Wp = W + (size_t)(nBase + arow) * K + aseg;

  float4 ra0 = *(const float4*)(Ap);
  float4 ra1 = *(const float4*)(Ap + 4);
  float4 rw0 = *(const float4*)(Wp);
  float4 rw1 = *(const float4*)(Wp + 4);

  float acc[2][2][4] = {};
  int nIter = K / GBK;
  int buf = 0;

  for (int it = 0; it < nIter; ++it) {
    {
      uint4 t;
      t.x = f2tf(ra0.x); t.y = f2tf(ra0.y); t.z = f2tf(ra0.z); t.w = f2tf(ra0.w);
      *(uint4*)&As[buf][arow][aseg] = t;
      t.x = f2tf(ra1.x); t.y = f2tf(ra1.y); t.z = f2tf(ra1.z); t.w = f2tf(ra1.w);
      *(uint4*)&As[buf][arow][aseg + 4] = t;
      t.x = f2tf(rw0.x); t.y = f2tf(rw0.y); t.z = f2tf(rw0.z); t.w = f2tf(rw0.w);
      *(uint4*)&Ws[buf][arow][aseg] = t;
      t.x = f2tf(rw1.x); t.y = f2tf(rw1.y); t.z = f2tf(rw1.z); t.w = f2tf(rw1.w);
      *(uint4*)&Ws[buf][arow][aseg + 4] = t;
    }
    __syncthreads();

    if (it + 1 < nIter) {
      const float* Ap2 = Ap + (it + 1) * GBK;
      const float* Wp2 = Wp + (it + 1) * GBK;
      ra0 = *(const float4*)(Ap2);
      ra1 = *(const float4*)(Ap2 + 4);
      rw0 = *(const float4*)(Wp2);
      rw1 = *(const float4*)(Wp2 + 4);
    }

#pragma unroll
    for (int ka = 0; ka < 4; ka++) {
      uint32_t a[2][4];
#pragma unroll
      for (int im = 0; im < 2; im++) {
        int row = wm * 32 + im * 16 + r;
        a[im][0] = As[buf][row][ka * 8 + c];
        a[im][1] = As[buf][row + 8][ka * 8 + c];
        a[im][2] = As[buf][row][ka * 8 + c + 4];
        a[im][3] = As[buf][row + 8][ka * 8 + c + 4];
      }
#pragma unroll
      for (int in_ = 0; in_ < 2; in_++) {
        int nrow = wn * 16 + in_ * 8 + r;
        uint32_t b0 = Ws[buf][nrow][ka * 8 + c];
        uint32_t b1 = Ws[buf][nrow][ka * 8 + c + 4];
        mma8(acc[0][in_], a[0][0], a[0][1], a[0][2], a[0][3], b0, b1);
        mma8(acc[1][in_], a[1][0], a[1][1], a[1][2], a[1][3], b0, b1);
      }
    }
    __syncthreads();
    buf ^= 1;
  }

#pragma unroll
  for (int im = 0; im < 2; im++) {
#pragma unroll
    for (int in_ = 0; in_ < 2; in_++) {
      int row = mBase + wm * 32 + im * 16 + r;
      int col = nBase + wn * 16 + in_ * 8 + 2 * c;
      float2 v0 = make_float2(acc[im][in_][0], acc[im][in_][1]);
      float2 v1 = make_float2(acc[im][in_][2], acc[im][in_][3]);
      *(float2*)&C[(size_t)row * N + col] = v0;
      *(float2*)&C[(size_t)(row + 8) * N + col] = v1;
    }
  }
}

// ---------------------------------------------------------------------------
// RoPE on q (16 heads) and k (4 heads), in place.
// ---------------------------------------------------------------------------
__global__ __launch_bounds__(256) void rope_kernel(const float* __restrict__ freqs) {
  int idx = blockIdx.x * blockDim.x + threadIdx.x;
  int i = idx & 31;
  int h = (idx >> 5) & 15;
  int bt = idx >> 9;
  int t = bt & (TT - 1);
  float cs = freqs[(t * 32 + i) * 2];
  float sn = freqs[(t * 32 + i) * 2 + 1];
  float* qp = &g_q[((size_t)bt * NH + h) * DH + 2 * i];
  float re = qp[0], im = qp[1];
  qp[0] = re * cs - im * sn;
  qp[1] = re * sn + im * cs;
  if (h < NKV) {
    float* kp = &g_k[((size_t)bt * NKV + h) * DH + 2 * i];
    float kre = kp[0], kim = kp[1];
    kp[0] = kre * cs - kim * sn;
    kp[1] = kre * sn + kim * cs;
  }
}

// ---------------------------------------------------------------------------
// Causal flash attention, tf32 MMA. CTA = (q-tile 64, b*H+h), 128 threads.
// KV tiles of 32. Warp owns 16 query rows. P fragment converted C->A via shfl.
// ---------------------------------------------------------------------------
__global__ __launch_bounds__(128) void attn_mma() {
  __shared__ uint32_t Qs[64][68];
  __shared__ uint32_t Ks[32][68];
  __shared__ uint32_t Vs[32][72];
  int tid = threadIdx.x, lane = tid & 31, wid = tid >> 5;
  int bh = blockIdx.y;
  int b = bh >> 4, h = bh & 15, kvh = h >> 2;
  int q0 = blockIdx.x << 6;
  int r = lane >> 2, c = lane & 3;

  // Load Q tile (scale folded in), tf32 convert.
  for (int i = tid; i < 1024; i += 128) {   // 64 rows x 16 float4
    int row = i >> 4, d = (i & 15) * 4;
    float4 v = *(const float4*)&g_q[(((size_t)b * TT + q0 + row) * NH + h) * DH + d];
    uint4 t;
    t.x = f2tf(v.x * 0.125f); t.y = f2tf(v.y * 0.125f);
    t.z = f2tf(v.z * 0.125f); t.w = f2tf(v.w * 0.125f);
    *(uint4*)&Qs[row][d] = t;
  }

  float o[8][4] = {};
  float m0 = -1e30f, m1 = -1e30f;
  float l0 = 0.f, l1 = 0.f;
  int qrow0 = q0 + wid * 16 + r;
  int nk = q0 + 64;

  for (int k0 = 0; k0 < nk; k0 += 32) {
    __syncthreads();
    for (int i = tid; i < 512; i += 128) {  // 32 rows x 16 float4
      int row = i >> 4, d = (i & 15) * 4;
      size_t base = (((size_t)b * TT + k0 + row) * NKV + kvh) * DH + d;
      float4 kv = *(const float4*)&g_k[base];
      float4 vv = *(const float4*)&g_v[base];
      uint4 t;
      t.x = f2tf(kv.x); t.y = f2tf(kv.y); t.z = f2tf(kv.z); t.w = f2tf(kv.w);
      *(uint4*)&Ks[row][d] = t;
      t.x = f2tf(vv.x); t.y = f2tf(vv.y); t.z = f2tf(vv.z); t.w = f2tf(vv.w);
      *(uint4*)&Vs[row][d] = t;
    }
    __syncthreads();

    // S = Q K^T  (warp: 16 rows x 32 keys, 4 n-atoms)
    float s[4][4] = {};
#pragma unroll
    for (int ka = 0; ka < 8; ka++) {
      uint32_t a0 = Qs[wid * 16 + r][ka * 8 + c];
      uint32_t a1 = Qs[wid * 16 + r + 8][ka * 8 + c];
      uint32_t a2 = Qs[wid * 16 + r][ka * 8 + c + 4];
      uint32_t a3 = Qs[wid * 16 + r + 8][ka * 8 + c + 4];
#pragma unroll
      for (int na = 0; na < 4; na++) {
        uint32_t b0 = Ks[na * 8 + r][ka * 8 + c];
        uint32_t b1 = Ks[na * 8 + r][ka * 8 + c + 4];
        mma8(s[na], a0, a1, a2, a3, b0, b1);
      }
    }

    // Causal mask (only tiles that touch the diagonal)
    if (k0 + 31 > q0 + wid * 16) {
#pragma unroll
      for (int na = 0; na < 4; na++) {
        int key = k0 + na * 8 + 2 * c;
        if (key     > qrow0)     s[na][0] = -1e9f;
        if (key + 1 > qrow0)     s[na][1] = -1e9f;
        if (key     > qrow0 + 8) s[na][2] = -1e9f;
        if (key + 1 > qrow0 + 8) s[na][3] = -1e9f;
      }
    }

    // Online softmax (rows r and r+8; quad lanes share a row)
    float mx0 = -1e30f, mx1 = -1e30f;
#pragma unroll
    for (int na = 0; na < 4; na++) {
      mx0 = fmaxf(mx0, fmaxf(s[na][0], s[na][1]));
      mx1 = fmaxf(mx1, fmaxf(s[na][2], s[na][3]));
    }
    mx0 = fmaxf(mx0, __shfl_xor_sync(0xffffffffu, mx0, 1));
    mx0 = fmaxf(mx0, __shfl_xor_sync(0xffffffffu, mx0, 2));
    mx1 = fmaxf(mx1, __shfl_xor_sync(0xffffffffu, mx1, 1));
    mx1 = fmaxf(mx1, __shfl_xor_sync(0xffffffffu, mx1, 2));
    float mn0 = fmaxf(m0, mx0), mn1 = fmaxf(m1, mx1);
    float sf0 = __expf(m0 - mn0), sf1 = __expf(m1 - mn1);
    m0 = mn0; m1 = mn1;
    float rs0 = 0.f, rs1 = 0.f;
#pragma unroll
    for (int na = 0; na < 4; na++) {
      s[na][0] = __expf(s[na][0] - mn0);
      s[na][1] = __expf(s[na][1] - mn0);
      s[na][2] = __expf(s[na][2] - mn1);
      s[na][3] = __expf(s[na][3] - mn1);
      rs0 += s[na][0] + s[na][1];
      rs1 += s[na][2] + s[na][3];
    }
    rs0 += __shfl_xor_sync(0xffffffffu, rs0, 1);
    rs0 += __shfl_xor_sync(0xffffffffu, rs0, 2);
    rs1 += __shfl_xor_sync(0xffffffffu, rs1, 1);
    rs1 += __shfl_xor_sync(0xffffffffu, rs1, 2);
    l0 = l0 * sf0 + rs0;
    l1 = l1 * sf1 + rs1;
#pragma unroll
    for (int na = 0; na < 8; na++) {
      o[na][0] *= sf0; o[na][1] *= sf0;
      o[na][2] *= sf1; o[na][3] *= sf1;
    }

    // O += P @ V ; P C-frag -> A-frag via shfl
    int src  = (lane & ~3) | (c >> 1);
    int src2 = (lane & ~3) | ((c >> 1) + 2);
#pragma unroll
    for (int ka = 0; ka < 4; ka++) {
      uint32_t p0 = f2tf(s[ka][0]), p1 = f2tf(s[ka][1]);
      uint32_t p2 = f2tf(s[ka][2]), p3 = f2tf(s[ka][3]);
      uint32_t v0, v1, a0, a1, a2, a3;
      v0 = __shfl_sync(0xffffffffu, p0, src);
      v1 = __shfl_sync(0xffffffffu, p1, src);
      a0 = (c & 1) ? v1 : v0;
      v0 = __shfl_sync(0xffffffffu, p2, src);
      v1 = __shfl_sync(0xffffffffu, p3, src);
      a1 = (c & 1) ? v1 : v0;
      v0 = __shfl_sync(0xffffffffu, p0, src2);
      v1 = __shfl_sync(0xffffffffu, p1, src2);
      a2 = (c & 1) ? v1 : v0;
      v0 = __shfl_sync(0xffffffffu, p2, src2);
      v1 = __shfl_sync(0xffffffffu, p3, src2);
      a3 = (c & 1) ? v1 : v0;
#pragma unroll
      for (int na = 0; na < 8; na++) {
        uint32_t b0 = Vs[ka * 8 + c][na * 8 + r];
        uint32_t b1 = Vs[ka * 8 + c + 4][na * 8 + r];
        mma8(o[na], a0, a1, a2, a3, b0, b1);
      }
    }
  }

  float inv0 = 1.f / l0, inv1 = 1.f / l1;
#pragma unroll
  for (int na = 0; na < 8; na++) {
    int row = q0 + wid * 16 + r;
    int col = na * 8 + 2 * c;
    float2 v0 = make_float2(o[na][0] * inv0, o[na][1] * inv0);
    float2 v1 = make_float2(o[na][2] * inv1, o[na][3] * inv1);
    *(float2*)&g_ao[(((size_t)b * TT + row) * NH + h) * DH + col] = v0;
    *(float2*)&g_ao[(((size_t)b * TT + row + 8) * NH + h) * DH + col] = v1;
  }
}

// ---------------------------------------------------------------------------
// Launch
// ---------------------------------------------------------------------------
extern "C" void kernel_launch(void* const* d_in, const int* in_sizes, int n_in,
                              void* d_out, int out_size) {
  const float* x     = (const float*)d_in[0];
  const float* freqs = (const float*)d_in[1];
  const float* w_q   = (const float*)d_in[3];
  const float* w_k   = (const float*)d_in[4];
  const float* w_v   = (const float*)d_in[5];
  const float* w_o   = (const float*)d_in[6];
  float* out = (float*)d_out;

  float *pq, *pk, *pv, *pao;
  cudaGetSymbolAddress((void**)&pq,  g_q);
  cudaGetSymbolAddress((void**)&pk,  g_k);
  cudaGetSymbolAddress((void**)&pv,  g_v);
  cudaGetSymbolAddress((void**)&pao, g_ao);

  gemm_mma<<<dim3((NH*DH)/GBN,  MM/GBM), 256>>>(x, w_q, pq, NH*DH,  DD);
  gemm_mma<<<dim3((NKV*DH)/GBN, MM/GBM), 256>>>(x, w_k, pk, NKV*DH, DD);
  gemm_mma<<<dim3((NKV*DH)/GBN, MM/GBM), 256>>>(x, w_v, pv, NKV*DH, DD);

  rope_kernel<<<(MM*NH*32)/256, 256>>>(freqs);

  attn_mma<<<dim3(TT/64, BB*NH), 128>>>();

  gemm_mma<<<dim3(DD/GBN, MM/GBM), 256>>>(pao, w_o, out, DD, DD);
}